// round 2
// baseline (speedup 1.0000x reference)
#include <cuda_runtime.h>

#define EPSF 1e-6f
#define N_  4
#define L_  4096
#define H_  16
#define D_  64
#define NH  64
#define RS  1024            /* row stride in floats = H*D */
#define PER_N (L_*H_*D_)    /* 4194304 */

// ---------------- scratch (no allocation allowed -> device globals) --------
__device__ float    g_qsum [NH*D_];
__device__ float    g_ksum [NH*D_];
__device__ float    g_qnsum[NH*D_];
__device__ float    g_knsum[NH*D_];
__device__ float    g_nrow [NH*L_];
__device__ float    g_rowfac[NH*L_];
__device__ float    g_cr   [NH*L_];
__device__ unsigned g_crmax[NH];
__device__ float    g_expsum[NH];
__device__ float    g_kv   [NH*D_*D_];

__device__ __forceinline__ float sigmoidf(float x) {
    return 1.0f / (1.0f + __expf(-x));
}
__device__ __forceinline__ int head_base(int nh) {
    int n = nh >> 4, h = nh & 15;
    return n * PER_N + h * D_;
}

// ---------------- K0: zero accumulators ------------------------------------
__global__ void __launch_bounds__(256) k0_zero() {
    int tid = blockIdx.x * blockDim.x + threadIdx.x;
    int stride = gridDim.x * blockDim.x;
    for (int i = tid; i < NH*D_; i += stride) {
        g_qsum[i] = 0.f; g_ksum[i] = 0.f; g_qnsum[i] = 0.f; g_knsum[i] = 0.f;
    }
    for (int i = tid; i < NH*D_*D_; i += stride) g_kv[i] = 0.f;
    for (int i = tid; i < NH; i += stride) { g_crmax[i] = 0u; g_expsum[i] = 0.f; }
}

// ---------------- K1: q_sum / k_sum (sigmoid applied) -----------------------
__global__ void __launch_bounds__(256) k1_sums(const float* __restrict__ Q,
                                               const float* __restrict__ K) {
    int nh = blockIdx.x;        // 64
    int chunk = blockIdx.y;     // 16 chunks of 256 rows
    int t = threadIdx.x;        // 256
    int col = t & 63;
    int rg  = t >> 6;           // 0..3
    const int base = head_base(nh);
    float qs = 0.f, ks = 0.f;
    int r0 = chunk * 256;
    for (int r = r0 + rg; r < r0 + 256; r += 4) {
        int off = base + r * RS + col;
        qs += sigmoidf(Q[off]);
        ks += sigmoidf(K[off]);
    }
    __shared__ float sq_[256], sk_[256];
    sq_[t] = qs; sk_[t] = ks;
    __syncthreads();
    if (t < 64) {
        float a = sq_[t] + sq_[t+64] + sq_[t+128] + sq_[t+192];
        float b = sk_[t] + sk_[t+64] + sk_[t+128] + sk_[t+192];
        atomicAdd(&g_qsum[nh*64 + t], a);
        atomicAdd(&g_ksum[nh*64 + t], b);
    }
}

// ---------------- K2: normalizers + qn_sum/kn_sum ---------------------------
__global__ void __launch_bounds__(256) k2_norm(const float* __restrict__ Q,
                                               const float* __restrict__ K) {
    int nh = blockIdx.x, chunk = blockIdx.y;
    int t = threadIdx.x;
    int lane = t & 31, w = t >> 5;   // 8 warps
    const int base = head_base(nh);
    __shared__ float ksum_s[64], qsum_s[64];
    __shared__ float qn_s[64], kn_s[64];
    if (t < 64) {
        ksum_s[t] = g_ksum[nh*64 + t] + EPSF;
        qsum_s[t] = g_qsum[nh*64 + t] + EPSF;
        qn_s[t] = 0.f; kn_s[t] = 0.f;
    }
    __syncthreads();
    float ks0 = ksum_s[2*lane], ks1 = ksum_s[2*lane+1];
    float qs0 = qsum_s[2*lane], qs1 = qsum_s[2*lane+1];
    float qn0 = 0.f, qn1 = 0.f, kn0 = 0.f, kn1 = 0.f;
    int r0 = chunk * 256;
    for (int r = r0 + w; r < r0 + 256; r += 8) {
        const float2 q2 = *(const float2*)(Q + base + r*RS + 2*lane);
        const float2 k2 = *(const float2*)(K + base + r*RS + 2*lane);
        float sq0 = sigmoidf(q2.x), sq1 = sigmoidf(q2.y);
        float sk0 = sigmoidf(k2.x), sk1 = sigmoidf(k2.y);
        float dq = (sq0 + EPSF) * ks0 + (sq1 + EPSF) * ks1;
        float dk = (sk0 + EPSF) * qs0 + (sk1 + EPSF) * qs1;
        #pragma unroll
        for (int o = 16; o; o >>= 1) {
            dq += __shfl_xor_sync(0xffffffffu, dq, o);
            dk += __shfl_xor_sync(0xffffffffu, dk, o);
        }
        float nr = 1.0f / dq;
        float nc = 1.0f / dk;
        if (lane == 0) g_nrow[nh*L_ + r] = nr;
        qn0 += sq0 * nr; qn1 += sq1 * nr;
        kn0 += sk0 * nc; kn1 += sk1 * nc;
    }
    atomicAdd(&qn_s[2*lane],   qn0);
    atomicAdd(&qn_s[2*lane+1], qn1);
    atomicAdd(&kn_s[2*lane],   kn0);
    atomicAdd(&kn_s[2*lane+1], kn1);
    __syncthreads();
    if (t < 64) {
        atomicAdd(&g_qnsum[nh*64 + t], qn_s[t]);
        atomicAdd(&g_knsum[nh*64 + t], kn_s[t]);
    }
}

// ---------------- K3: row_refine, col_refine logits + per-head max ----------
__global__ void __launch_bounds__(256) k3_refine(const float* __restrict__ Q,
                                                 const float* __restrict__ K) {
    int nh = blockIdx.x, chunk = blockIdx.y;
    int t = threadIdx.x;
    int lane = t & 31, w = t >> 5;
    const int base = head_base(nh);
    __shared__ float kns[64], qns[64];
    if (t < 64) {
        kns[t] = g_knsum[nh*64 + t] + EPSF;
        qns[t] = g_qnsum[nh*64 + t] + EPSF;
    }
    __syncthreads();
    float kn0 = kns[2*lane], kn1 = kns[2*lane+1];
    float qn0 = qns[2*lane], qn1 = qns[2*lane+1];
    float mx = 0.f;  // cr is strictly positive
    int r0 = chunk * 256;
    for (int r = r0 + w; r < r0 + 256; r += 8) {
        const float2 q2 = *(const float2*)(Q + base + r*RS + 2*lane);
        const float2 k2 = *(const float2*)(K + base + r*RS + 2*lane);
        float sq0 = sigmoidf(q2.x), sq1 = sigmoidf(q2.y);
        float sk0 = sigmoidf(k2.x), sk1 = sigmoidf(k2.y);
        float dr = (sq0 + EPSF) * kn0 + (sq1 + EPSF) * kn1;
        float dc = (sk0 + EPSF) * qn0 + (sk1 + EPSF) * qn1;
        #pragma unroll
        for (int o = 16; o; o >>= 1) {
            dr += __shfl_xor_sync(0xffffffffu, dr, o);
            dc += __shfl_xor_sync(0xffffffffu, dc, o);
        }
        if (lane == 0) {
            // L/S == 1.0 here
            g_rowfac[nh*L_ + r] = g_nrow[nh*L_ + r] * sigmoidf(dr);
            g_cr[nh*L_ + r] = dc;
        }
        mx = fmaxf(mx, dc);
    }
    if (lane == 0) atomicMax(&g_crmax[nh], __float_as_uint(mx));
}

// ---------------- K4: softmax denominator -----------------------------------
__global__ void __launch_bounds__(256) k4_expsum() {
    int nh = blockIdx.x, t = threadIdx.x;
    float mx = __uint_as_float(g_crmax[nh]);
    float s = 0.f;
    int r0 = blockIdx.y * 1024;
    for (int r = r0 + t; r < r0 + 1024; r += 256)
        s += __expf(g_cr[nh*L_ + r] - mx);
    __shared__ float sh[256];
    sh[t] = s;
    __syncthreads();
    for (int o = 128; o; o >>= 1) {
        if (t < o) sh[t] += sh[t + o];
        __syncthreads();
    }
    if (t == 0) atomicAdd(&g_expsum[nh], sh[0]);
}

// ---------------- K5: kv[d][e] = sum_s (w*sigmoid(K))[s,d] * V[s,e] ----------
__global__ void __launch_bounds__(256) k5_kv(const float* __restrict__ K,
                                             const float* __restrict__ V) {
    int nh = blockIdx.x, chunk = blockIdx.y; // 8 chunks x 512 rows
    int t = threadIdx.x;
    const int base = head_base(nh);
    int tx = t & 15, ty = t >> 4;
    int e0 = tx * 4, d0 = ty * 4;
    float mx = __uint_as_float(g_crmax[nh]);
    float scale = (float)L_ / g_expsum[nh];

    __shared__ __align__(16) float k_sh[8][64];
    __shared__ __align__(16) float v_sh[8][64];
    float acc[4][4] = {};

    int lrow = t >> 5;        // 0..7
    int lcol = (t & 31) * 2;  // 0..62
    int r0 = chunk * 512;

    for (int rb = r0; rb < r0 + 512; rb += 8) {
        __syncthreads();      // protect shared from previous stage's readers
        int r = rb + lrow;
        float wgt = __expf(g_cr[nh*L_ + r] - mx) * scale;
        const float2 k2 = *(const float2*)(K + base + r*RS + lcol);
        const float2 v2 = *(const float2*)(V + base + r*RS + lcol);
        k_sh[lrow][lcol]   = sigmoidf(k2.x) * wgt;
        k_sh[lrow][lcol+1] = sigmoidf(k2.y) * wgt;
        v_sh[lrow][lcol]   = v2.x;
        v_sh[lrow][lcol+1] = v2.y;
        __syncthreads();
        #pragma unroll
        for (int s = 0; s < 8; s++) {
            float4 a4 = *(const float4*)&k_sh[s][d0];
            float4 b4 = *(const float4*)&v_sh[s][e0];
            float a[4] = {a4.x, a4.y, a4.z, a4.w};
            float b[4] = {b4.x, b4.y, b4.z, b4.w};
            #pragma unroll
            for (int i = 0; i < 4; i++)
                #pragma unroll
                for (int j = 0; j < 4; j++)
                    acc[i][j] += a[i] * b[j];
        }
    }
    #pragma unroll
    for (int i = 0; i < 4; i++)
        #pragma unroll
        for (int j = 0; j < 4; j++)
            atomicAdd(&g_kv[nh*4096 + (d0+i)*64 + (e0+j)], acc[i][j]);
}

// ---------------- K6: out = (sigmoid(Q) @ kv) * rowfac ----------------------
__global__ void __launch_bounds__(256) k6_out(const float* __restrict__ Q,
                                              float* __restrict__ O) {
    int nh = blockIdx.x, chunk = blockIdx.y; // 64 chunks x 64 rows
    int t = threadIdx.x;
    const int base = head_base(nh);

    __shared__ __align__(16) float kv_sh[64*64];
    __shared__ float q_sh[64][65];

    // load kv tile (4096 floats)
    for (int i = t * 4; i < 4096; i += 1024)
        *(float4*)&kv_sh[i] = *(const float4*)&g_kv[nh*4096 + i];

    // load 64 Q rows (sigmoid applied)
    int r0 = chunk * 64;
    for (int i = t; i < 64 * 16; i += 256) {
        int row = i >> 4, c = (i & 15) * 4;
        float4 q4 = *(const float4*)(Q + base + (r0 + row)*RS + c);
        q_sh[row][c]   = sigmoidf(q4.x);
        q_sh[row][c+1] = sigmoidf(q4.y);
        q_sh[row][c+2] = sigmoidf(q4.z);
        q_sh[row][c+3] = sigmoidf(q4.w);
    }
    __syncthreads();

    int tx = t & 15, ty = t >> 4;
    int e0 = tx * 4;
    int rr0 = ty * 4;
    float acc[4][4] = {};
    #pragma unroll 4
    for (int d = 0; d < 64; d++) {
        float4 b4 = *(const float4*)&kv_sh[d*64 + e0];
        #pragma unroll
        for (int i = 0; i < 4; i++) {
            float a = q_sh[rr0 + i][d];
            acc[i][0] += a * b4.x;
            acc[i][1] += a * b4.y;
            acc[i][2] += a * b4.z;
            acc[i][3] += a * b4.w;
        }
    }
    #pragma unroll
    for (int i = 0; i < 4; i++) {
        int r = r0 + rr0 + i;
        float f = g_rowfac[nh*L_ + r];
        float4 o;
        o.x = acc[i][0] * f;
        o.y = acc[i][1] * f;
        o.z = acc[i][2] * f;
        o.w = acc[i][3] * f;
        *(float4*)(O + base + r*RS + e0) = o;
    }
}

// ---------------- launch ----------------------------------------------------
extern "C" void kernel_launch(void* const* d_in, const int* in_sizes, int n_in,
                              void* d_out, int out_size) {
    const float* Q = (const float*)d_in[0];
    const float* K = (const float*)d_in[1];
    const float* V = (const float*)d_in[2];
    float* O = (float*)d_out;

    k0_zero   <<<dim3(256),      256>>>();
    k1_sums   <<<dim3(NH, 16),   256>>>(Q, K);
    k2_norm   <<<dim3(NH, 16),   256>>>(Q, K);
    k3_refine <<<dim3(NH, 16),   256>>>(Q, K);
    k4_expsum <<<dim3(NH, 4),    256>>>();
    k5_kv     <<<dim3(NH, 8),    256>>>(K, V);
    k6_out    <<<dim3(NH, 64),   256>>>(Q, O);
}

// round 3
// speedup vs baseline: 1.4235x; 1.4235x over previous
#include <cuda_runtime.h>
#include <cuda_fp16.h>

#define EPSF 1e-6f
#define N_  4
#define L_  4096
#define H_  16
#define D_  64
#define NH  64
#define RS  1024            /* row stride in floats = H*D */
#define PER_N (L_*H_*D_)

// ---------------- scratch (device globals; no allocation allowed) ----------
__device__ float    g_qsum [NH*D_];
__device__ float    g_ksum [NH*D_];
__device__ float    g_qnsum[NH*D_];
__device__ float    g_knsum[NH*D_];
__device__ float    g_nrow [NH*L_];
__device__ float    g_rowfac[NH*L_];
__device__ float    g_cr   [NH*L_];
__device__ unsigned g_crmax[NH];
__device__ float    g_expsum[NH];
__device__ float    g_kv   [NH*D_*D_];
// fp16 sigmoid scratch: [nh][L][64] contiguous (32 MiB each)
__device__ __half   g_sq[(size_t)NH*L_*D_];
__device__ __half   g_sk[(size_t)NH*L_*D_];

__device__ __forceinline__ float sigmoidf(float x) {
    return 1.0f / (1.0f + __expf(-x));
}
__device__ __forceinline__ int head_base(int nh) {
    int n = nh >> 4, h = nh & 15;
    return n * PER_N + h * D_;
}

// f32x2 packed-FMA helpers (sm_10x)
__device__ __forceinline__ unsigned long long pk2(float x, float y) {
    unsigned long long r;
    asm("mov.b64 %0, {%1, %2};" : "=l"(r) : "f"(x), "f"(y));
    return r;
}
__device__ __forceinline__ void upk2(unsigned long long v, float& x, float& y) {
    asm("mov.b64 {%0, %1}, %2;" : "=f"(x), "=f"(y) : "l"(v));
}
__device__ __forceinline__ unsigned long long ffma2(unsigned long long a,
                                                    unsigned long long b,
                                                    unsigned long long c) {
    unsigned long long d;
    asm("fma.rn.f32x2 %0, %1, %2, %3;" : "=l"(d) : "l"(a), "l"(b), "l"(c));
    return d;
}

struct __align__(8) H4 { __half2 a, b; };

// ---------------- K0: zero accumulators ------------------------------------
__global__ void __launch_bounds__(256) k0_zero() {
    int tid = blockIdx.x * blockDim.x + threadIdx.x;
    int stride = gridDim.x * blockDim.x;
    for (int i = tid; i < NH*D_; i += stride) {
        g_qsum[i] = 0.f; g_ksum[i] = 0.f; g_qnsum[i] = 0.f; g_knsum[i] = 0.f;
    }
    for (int i = tid; i < NH*D_*D_; i += stride) g_kv[i] = 0.f;
    for (int i = tid; i < NH; i += stride) { g_crmax[i] = 0u; g_expsum[i] = 0.f; }
}

// ---------------- K1: sigmoid -> fp16 scratch + column sums -----------------
__global__ void __launch_bounds__(256) k1_sums(const float* __restrict__ Q,
                                               const float* __restrict__ K) {
    int nh = blockIdx.x, chunk = blockIdx.y;   // 16 chunks of 256 rows
    int t = threadIdx.x;
    int col = (t & 15) * 4;    // 4 columns per thread
    int rg  = t >> 4;          // 16 row groups
    const int base = head_base(nh);
    const size_t sbase = (size_t)nh * L_ * D_;
    float qs[4] = {}, ks[4] = {};
    int r0 = chunk * 256;
    #pragma unroll 4
    for (int it = 0; it < 16; it++) {
        int r = r0 + it * 16 + rg;
        int off = base + r * RS + col;
        float4 q4 = *(const float4*)(Q + off);
        float4 k4 = *(const float4*)(K + off);
        float sq0 = sigmoidf(q4.x), sq1 = sigmoidf(q4.y);
        float sq2 = sigmoidf(q4.z), sq3 = sigmoidf(q4.w);
        float sk0 = sigmoidf(k4.x), sk1 = sigmoidf(k4.y);
        float sk2 = sigmoidf(k4.z), sk3 = sigmoidf(k4.w);
        qs[0] += sq0; qs[1] += sq1; qs[2] += sq2; qs[3] += sq3;
        ks[0] += sk0; ks[1] += sk1; ks[2] += sk2; ks[3] += sk3;
        H4 hq; hq.a = __floats2half2_rn(sq0, sq1); hq.b = __floats2half2_rn(sq2, sq3);
        H4 hk; hk.a = __floats2half2_rn(sk0, sk1); hk.b = __floats2half2_rn(sk2, sk3);
        size_t sidx = sbase + (size_t)r * D_ + col;
        *(H4*)(g_sq + sidx) = hq;
        *(H4*)(g_sk + sidx) = hk;
    }
    __shared__ float qsum_s[64], ksum_s[64];
    if (t < 64) { qsum_s[t] = 0.f; ksum_s[t] = 0.f; }
    __syncthreads();
    #pragma unroll
    for (int i = 0; i < 4; i++) {
        atomicAdd(&qsum_s[col + i], qs[i]);
        atomicAdd(&ksum_s[col + i], ks[i]);
    }
    __syncthreads();
    if (t < 64) {
        atomicAdd(&g_qsum[nh*64 + t], qsum_s[t]);
        atomicAdd(&g_ksum[nh*64 + t], ksum_s[t]);
    }
}

// ---------------- K2: nrow + qn_sum/kn_sum (fp16 scratch, tiled) ------------
__global__ void __launch_bounds__(256) k2_norm() {
    int nh = blockIdx.x, tile = blockIdx.y;  // 64 tiles x 64 rows
    int t = threadIdx.x;
    const size_t sbase = (size_t)nh * L_ * D_;
    int r0 = tile * 64;

    __shared__ float sq_s[64][65], sk_s[64][65];
    __shared__ float ks_c[64], qs_c[64];
    __shared__ float nr_s[64], nc_s[64];
    __shared__ float qn_p[4][64], kn_p[4][64];

    if (t < 64) {
        ks_c[t] = g_ksum[nh*64 + t] + EPSF;
        qs_c[t] = g_qsum[nh*64 + t] + EPSF;
    }
    // load + convert: each thread 16 halves per tensor
    {
        int row = t >> 2, col0 = (t & 3) * 16;
        size_t gidx = sbase + (size_t)(r0 + row) * D_ + col0;
        uint4 uq0 = *(const uint4*)(g_sq + gidx);
        uint4 uq1 = *(const uint4*)(g_sq + gidx + 8);
        uint4 uk0 = *(const uint4*)(g_sk + gidx);
        uint4 uk1 = *(const uint4*)(g_sk + gidx + 8);
        unsigned uq[8] = {uq0.x,uq0.y,uq0.z,uq0.w, uq1.x,uq1.y,uq1.z,uq1.w};
        unsigned uk[8] = {uk0.x,uk0.y,uk0.z,uk0.w, uk1.x,uk1.y,uk1.z,uk1.w};
        #pragma unroll
        for (int i = 0; i < 8; i++) {
            float2 fq = __half22float2(*(__half2*)&uq[i]);
            float2 fk = __half22float2(*(__half2*)&uk[i]);
            sq_s[row][col0 + 2*i]     = fq.x;
            sq_s[row][col0 + 2*i + 1] = fq.y;
            sk_s[row][col0 + 2*i]     = fk.x;
            sk_s[row][col0 + 2*i + 1] = fk.y;
        }
    }
    __syncthreads();
    // per-row dots: 4 threads per row, 16 cols each
    {
        int row = t >> 2, c0 = (t & 3) * 16;
        float dq = 0.f, dk = 0.f;
        #pragma unroll
        for (int i = 0; i < 16; i++) {
            int c = c0 + i;
            dq += (sq_s[row][c] + EPSF) * ks_c[c];
            dk += (sk_s[row][c] + EPSF) * qs_c[c];
        }
        dq += __shfl_xor_sync(0xffffffffu, dq, 1);
        dq += __shfl_xor_sync(0xffffffffu, dq, 2);
        dk += __shfl_xor_sync(0xffffffffu, dk, 1);
        dk += __shfl_xor_sync(0xffffffffu, dk, 2);
        if ((t & 3) == 0) {
            float nr = 1.0f / dq, nc = 1.0f / dk;
            nr_s[row] = nr; nc_s[row] = nc;
            g_nrow[nh*L_ + r0 + row] = nr;
        }
    }
    __syncthreads();
    // column sums: qn[d] += sq[r][d]*nr[r], kn[d] += sk[r][d]*nc[r]
    {
        int col = t & 63, rg = t >> 6;
        float qn = 0.f, kn = 0.f;
        #pragma unroll
        for (int i = 0; i < 16; i++) {
            int r = rg * 16 + i;
            qn += sq_s[r][col] * nr_s[r];
            kn += sk_s[r][col] * nc_s[r];
        }
        qn_p[rg][col] = qn; kn_p[rg][col] = kn;
    }
    __syncthreads();
    if (t < 64) {
        atomicAdd(&g_qnsum[nh*64 + t], qn_p[0][t] + qn_p[1][t] + qn_p[2][t] + qn_p[3][t]);
        atomicAdd(&g_knsum[nh*64 + t], kn_p[0][t] + kn_p[1][t] + kn_p[2][t] + kn_p[3][t]);
    }
}

// ---------------- K3: rowfac + cr + per-head max (fp16 scratch, tiled) ------
__global__ void __launch_bounds__(256) k3_refine() {
    int nh = blockIdx.x, tile = blockIdx.y;
    int t = threadIdx.x;
    const size_t sbase = (size_t)nh * L_ * D_;
    int r0 = tile * 64;

    __shared__ float sq_s[64][65], sk_s[64][65];
    __shared__ float kn_c[64], qn_c[64], nr_l[64];
    __shared__ float mx_s[8];

    if (t < 64) {
        kn_c[t] = g_knsum[nh*64 + t] + EPSF;
        qn_c[t] = g_qnsum[nh*64 + t] + EPSF;
        nr_l[t] = g_nrow[nh*L_ + r0 + t];
    }
    {
        int row = t >> 2, col0 = (t & 3) * 16;
        size_t gidx = sbase + (size_t)(r0 + row) * D_ + col0;
        uint4 uq0 = *(const uint4*)(g_sq + gidx);
        uint4 uq1 = *(const uint4*)(g_sq + gidx + 8);
        uint4 uk0 = *(const uint4*)(g_sk + gidx);
        uint4 uk1 = *(const uint4*)(g_sk + gidx + 8);
        unsigned uq[8] = {uq0.x,uq0.y,uq0.z,uq0.w, uq1.x,uq1.y,uq1.z,uq1.w};
        unsigned uk[8] = {uk0.x,uk0.y,uk0.z,uk0.w, uk1.x,uk1.y,uk1.z,uk1.w};
        #pragma unroll
        for (int i = 0; i < 8; i++) {
            float2 fq = __half22float2(*(__half2*)&uq[i]);
            float2 fk = __half22float2(*(__half2*)&uk[i]);
            sq_s[row][col0 + 2*i]     = fq.x;
            sq_s[row][col0 + 2*i + 1] = fq.y;
            sk_s[row][col0 + 2*i]     = fk.x;
            sk_s[row][col0 + 2*i + 1] = fk.y;
        }
    }
    __syncthreads();
    float mx = 0.f;  // cr strictly positive
    {
        int row = t >> 2, c0 = (t & 3) * 16;
        float dr = 0.f, dc = 0.f;
        #pragma unroll
        for (int i = 0; i < 16; i++) {
            int c = c0 + i;
            dr += (sq_s[row][c] + EPSF) * kn_c[c];
            dc += (sk_s[row][c] + EPSF) * qn_c[c];
        }
        dr += __shfl_xor_sync(0xffffffffu, dr, 1);
        dr += __shfl_xor_sync(0xffffffffu, dr, 2);
        dc += __shfl_xor_sync(0xffffffffu, dc, 1);
        dc += __shfl_xor_sync(0xffffffffu, dc, 2);
        if ((t & 3) == 0) {
            // L/S == 1 -> no extra scale on dr
            g_rowfac[nh*L_ + r0 + row] = nr_l[row] * sigmoidf(dr);
            g_cr[nh*L_ + r0 + row] = dc;
            mx = dc;
        }
    }
    // block max reduce
    #pragma unroll
    for (int o = 16; o; o >>= 1) mx = fmaxf(mx, __shfl_xor_sync(0xffffffffu, mx, o));
    if ((t & 31) == 0) mx_s[t >> 5] = mx;
    __syncthreads();
    if (t == 0) {
        float m = mx_s[0];
        #pragma unroll
        for (int i = 1; i < 8; i++) m = fmaxf(m, mx_s[i]);
        atomicMax(&g_crmax[nh], __float_as_uint(m));
    }
}

// ---------------- K4: softmax denominator -----------------------------------
__global__ void __launch_bounds__(256) k4_expsum() {
    int nh = blockIdx.x, t = threadIdx.x;
    float mx = __uint_as_float(g_crmax[nh]);
    float s = 0.f;
    int r0 = blockIdx.y * 1024;
    for (int r = r0 + t; r < r0 + 1024; r += 256)
        s += __expf(g_cr[nh*L_ + r] - mx);
    __shared__ float sh[256];
    sh[t] = s;
    __syncthreads();
    for (int o = 128; o; o >>= 1) {
        if (t < o) sh[t] += sh[t + o];
        __syncthreads();
    }
    if (t == 0) atomicAdd(&g_expsum[nh], sh[0]);
}

// ---------------- K5: kv = sigmoid(K)^T @ (w * V), f32x2 FMA ----------------
__global__ void __launch_bounds__(256) k5_kv(const float* __restrict__ K,
                                             const float* __restrict__ V) {
    int nh = blockIdx.x, chunk = blockIdx.y;  // 16 chunks x 256 rows
    int t = threadIdx.x;
    const int base = head_base(nh);
    int tx = t & 15, ty = t >> 4;
    int e0 = tx * 4, d0 = ty * 4;
    float mx = __uint_as_float(g_crmax[nh]);
    float scale = (float)L_ / g_expsum[nh];

    __shared__ __align__(16) float k_sh[16][68];
    __shared__ __align__(16) float v_sh[16][68];
    unsigned long long acc[4][2];
    #pragma unroll
    for (int i = 0; i < 4; i++) { acc[i][0] = 0ull; acc[i][1] = 0ull; }

    int lrow = t >> 4;          // 0..15 (1 row per thread per stage)
    int lcol = (t & 15) * 4;
    int r0 = chunk * 256;

    for (int rb = r0; rb < r0 + 256; rb += 16) {
        __syncthreads();
        int r = rb + lrow;
        float wgt = __expf(g_cr[nh*L_ + r] - mx) * scale;
        float4 k4 = *(const float4*)(K + base + r*RS + lcol);
        float4 v4 = *(const float4*)(V + base + r*RS + lcol);
        k_sh[lrow][lcol]   = sigmoidf(k4.x) * wgt;
        k_sh[lrow][lcol+1] = sigmoidf(k4.y) * wgt;
        k_sh[lrow][lcol+2] = sigmoidf(k4.z) * wgt;
        k_sh[lrow][lcol+3] = sigmoidf(k4.w) * wgt;
        *(float4*)&v_sh[lrow][lcol] = v4;
        __syncthreads();
        #pragma unroll
        for (int s = 0; s < 16; s++) {
            float4 a4 = *(const float4*)&k_sh[s][d0];
            float4 b4 = *(const float4*)&v_sh[s][e0];
            unsigned long long b01 = pk2(b4.x, b4.y);
            unsigned long long b23 = pk2(b4.z, b4.w);
            float a[4] = {a4.x, a4.y, a4.z, a4.w};
            #pragma unroll
            for (int i = 0; i < 4; i++) {
                unsigned long long ai = pk2(a[i], a[i]);
                acc[i][0] = ffma2(ai, b01, acc[i][0]);
                acc[i][1] = ffma2(ai, b23, acc[i][1]);
            }
        }
    }
    #pragma unroll
    for (int i = 0; i < 4; i++) {
        float x0, x1, x2, x3;
        upk2(acc[i][0], x0, x1);
        upk2(acc[i][1], x2, x3);
        float* dst = &g_kv[nh*4096 + (d0+i)*64 + e0];
        atomicAdd(dst+0, x0); atomicAdd(dst+1, x1);
        atomicAdd(dst+2, x2); atomicAdd(dst+3, x3);
    }
}

// ---------------- K6: out = (sigmoid(Q) @ kv) * rowfac, f32x2 FMA -----------
__global__ void __launch_bounds__(256) k6_out(const float* __restrict__ Q,
                                              float* __restrict__ O) {
    int nh = blockIdx.x, chunk = blockIdx.y;  // 64 chunks x 64 rows
    int t = threadIdx.x;
    const int base = head_base(nh);

    __shared__ __align__(16) float kv_sh[64*64];
    __shared__ float q_sh[64][65];

    for (int i = t * 4; i < 4096; i += 1024)
        *(float4*)&kv_sh[i] = *(const float4*)&g_kv[nh*4096 + i];

    int r0 = chunk * 64;
    for (int i = t; i < 64 * 16; i += 256) {
        int row = i >> 4, c = (i & 15) * 4;
        float4 q4 = *(const float4*)(Q + base + (r0 + row)*RS + c);
        q_sh[row][c]   = sigmoidf(q4.x);
        q_sh[row][c+1] = sigmoidf(q4.y);
        q_sh[row][c+2] = sigmoidf(q4.z);
        q_sh[row][c+3] = sigmoidf(q4.w);
    }
    __syncthreads();

    int tx = t & 15, ty = t >> 4;
    int e0 = tx * 4;
    int rr0 = ty * 4;
    unsigned long long acc[4][2];
    #pragma unroll
    for (int i = 0; i < 4; i++) { acc[i][0] = 0ull; acc[i][1] = 0ull; }
    #pragma unroll 8
    for (int d = 0; d < 64; d++) {
        float4 b4 = *(const float4*)&kv_sh[d*64 + e0];
        unsigned long long b01 = pk2(b4.x, b4.y);
        unsigned long long b23 = pk2(b4.z, b4.w);
        #pragma unroll
        for (int i = 0; i < 4; i++) {
            float a = q_sh[rr0 + i][d];
            unsigned long long ai = pk2(a, a);
            acc[i][0] = ffma2(ai, b01, acc[i][0]);
            acc[i][1] = ffma2(ai, b23, acc[i][1]);
        }
    }
    #pragma unroll
    for (int i = 0; i < 4; i++) {
        int r = r0 + rr0 + i;
        float f = g_rowfac[nh*L_ + r];
        float x0, x1, x2, x3;
        upk2(acc[i][0], x0, x1);
        upk2(acc[i][1], x2, x3);
        float4 o;
        o.x = x0 * f; o.y = x1 * f; o.z = x2 * f; o.w = x3 * f;
        *(float4*)(O + base + r*RS + e0) = o;
    }
}

// ---------------- launch ----------------------------------------------------
extern "C" void kernel_launch(void* const* d_in, const int* in_sizes, int n_in,
                              void* d_out, int out_size) {
    const float* Q = (const float*)d_in[0];
    const float* K = (const float*)d_in[1];
    const float* V = (const float*)d_in[2];
    float* O = (float*)d_out;

    k0_zero   <<<dim3(256),      256>>>();
    k1_sums   <<<dim3(NH, 16),   256>>>(Q, K);
    k2_norm   <<<dim3(NH, 64),   256>>>();
    k3_refine <<<dim3(NH, 64),   256>>>();
    k4_expsum <<<dim3(NH, 4),    256>>>();
    k5_kv     <<<dim3(NH, 16),   256>>>(K, V);
    k6_out    <<<dim3(NH, 64),   256>>>(Q, O);
}

// round 4
// speedup vs baseline: 1.6325x; 1.1469x over previous
#include <cuda_runtime.h>
#include <cuda_fp16.h>

#define EPSF 1e-6f
#define N_  4
#define L_  4096
#define H_  16
#define D_  64
#define NH  64
#define RS  1024            /* row stride in floats = H*D */
#define PER_N (L_*H_*D_)

// ---------------- scratch (device globals; no allocation allowed) ----------
__device__ float    g_qsum [NH*D_];
__device__ float    g_ksum [NH*D_];
__device__ float    g_qnsum[NH*D_];
__device__ float    g_knsum[NH*D_];
__device__ float    g_nrow [NH*L_];
__device__ float    g_rowfac[NH*L_];
__device__ float    g_cr   [NH*L_];
__device__ unsigned g_crmax[NH];
__device__ float    g_expsum[NH];
__device__ float    g_kv   [NH*D_*D_];
// fp16 sigmoid scratch: [nh][L][64] contiguous (32 MiB each)
__device__ __align__(16) __half g_sq[(size_t)NH*L_*D_];
__device__ __align__(16) __half g_sk[(size_t)NH*L_*D_];

__device__ __forceinline__ float sigmoidf(float x) {
    float t;
    asm("tanh.approx.f32 %0, %1;" : "=f"(t) : "f"(0.5f * x));
    return fmaf(0.5f, t, 0.5f);
}
__device__ __forceinline__ int head_base(int nh) {
    int n = nh >> 4, h = nh & 15;
    return n * PER_N + h * D_;
}
__device__ __forceinline__ float2 h22f2(unsigned u) {
    return __half22float2(*reinterpret_cast<__half2*>(&u));
}

// f32x2 packed-FMA helpers (sm_10x)
__device__ __forceinline__ unsigned long long pk2(float x, float y) {
    unsigned long long r;
    asm("mov.b64 %0, {%1, %2};" : "=l"(r) : "f"(x), "f"(y));
    return r;
}
__device__ __forceinline__ void upk2(unsigned long long v, float& x, float& y) {
    asm("mov.b64 {%0, %1}, %2;" : "=f"(x), "=f"(y) : "l"(v));
}
__device__ __forceinline__ unsigned long long ffma2(unsigned long long a,
                                                    unsigned long long b,
                                                    unsigned long long c) {
    unsigned long long d;
    asm("fma.rn.f32x2 %0, %1, %2, %3;" : "=l"(d) : "l"(a), "l"(b), "l"(c));
    return d;
}

struct __align__(8) H4 { __half2 a, b; };

// ---------------- K0: zero accumulators ------------------------------------
__global__ void __launch_bounds__(256) k0_zero() {
    int tid = blockIdx.x * blockDim.x + threadIdx.x;
    int stride = gridDim.x * blockDim.x;
    for (int i = tid; i < NH*D_; i += stride) {
        g_qsum[i] = 0.f; g_ksum[i] = 0.f; g_qnsum[i] = 0.f; g_knsum[i] = 0.f;
    }
    for (int i = tid; i < NH*D_*D_; i += stride) g_kv[i] = 0.f;
    for (int i = tid; i < NH; i += stride) { g_crmax[i] = 0u; g_expsum[i] = 0.f; }
}

// ---------------- K1: sigmoid -> fp16 scratch + column sums -----------------
__global__ void __launch_bounds__(256) k1_sums(const float* __restrict__ Q,
                                               const float* __restrict__ K) {
    int nh = blockIdx.x, chunk = blockIdx.y;   // 16 chunks of 256 rows
    int t = threadIdx.x;
    int col = (t & 15) * 4;
    int rg  = t >> 4;
    const int base = head_base(nh);
    const size_t sbase = (size_t)nh * L_ * D_;
    float qs[4] = {}, ks[4] = {};
    int r0 = chunk * 256;
    #pragma unroll 4
    for (int it = 0; it < 16; it++) {
        int r = r0 + it * 16 + rg;
        int off = base + r * RS + col;
        float4 q4 = *(const float4*)(Q + off);
        float4 k4 = *(const float4*)(K + off);
        float sq0 = sigmoidf(q4.x), sq1 = sigmoidf(q4.y);
        float sq2 = sigmoidf(q4.z), sq3 = sigmoidf(q4.w);
        float sk0 = sigmoidf(k4.x), sk1 = sigmoidf(k4.y);
        float sk2 = sigmoidf(k4.z), sk3 = sigmoidf(k4.w);
        qs[0] += sq0; qs[1] += sq1; qs[2] += sq2; qs[3] += sq3;
        ks[0] += sk0; ks[1] += sk1; ks[2] += sk2; ks[3] += sk3;
        H4 hq; hq.a = __floats2half2_rn(sq0, sq1); hq.b = __floats2half2_rn(sq2, sq3);
        H4 hk; hk.a = __floats2half2_rn(sk0, sk1); hk.b = __floats2half2_rn(sk2, sk3);
        size_t sidx = sbase + (size_t)r * D_ + col;
        *(H4*)(g_sq + sidx) = hq;
        *(H4*)(g_sk + sidx) = hk;
    }
    __shared__ float qsum_s[64], ksum_s[64];
    if (t < 64) { qsum_s[t] = 0.f; ksum_s[t] = 0.f; }
    __syncthreads();
    #pragma unroll
    for (int i = 0; i < 4; i++) {
        atomicAdd(&qsum_s[col + i], qs[i]);
        atomicAdd(&ksum_s[col + i], ks[i]);
    }
    __syncthreads();
    if (t < 64) {
        atomicAdd(&g_qsum[nh*64 + t], qsum_s[t]);
        atomicAdd(&g_ksum[nh*64 + t], ksum_s[t]);
    }
}

// ---------------- K2: nrow + qn_sum/kn_sum (register dots, no staging) ------
__global__ void __launch_bounds__(256) k2_norm() {
    int nh = blockIdx.x, tile = blockIdx.y;    // 16 tiles x 256 rows
    int t = threadIdx.x;
    const size_t sbase = (size_t)nh * L_ * D_;
    int r0 = tile * 256;

    __shared__ float ksc[64], qsc[64];
    __shared__ float nr_s[256], nc_s[256];
    __shared__ float qn_pf[8][66], kn_pf[8][66];
    __shared__ float epsq_s, epsk_s;

    if (t < 64) {
        ksc[t] = g_ksum[nh*64 + t] + EPSF;
        qsc[t] = g_qsum[nh*64 + t] + EPSF;
    }
    __syncthreads();
    if (t == 0) {
        float a = 0.f, b = 0.f;
        #pragma unroll
        for (int c = 0; c < 64; c++) { a += ksc[c]; b += qsc[c]; }
        epsq_s = EPSF * a;   // eps * sum(ksum+eps)
        epsk_s = EPSF * b;
    }
    __syncthreads();

    // Phase A: thread = row. Register dot against broadcast column vectors.
    {
        int r = r0 + t;
        const uint4* pq = (const uint4*)(g_sq + sbase + (size_t)r * D_);
        const uint4* pk = (const uint4*)(g_sk + sbase + (size_t)r * D_);
        float dq = 0.f, dk = 0.f;
        #pragma unroll
        for (int i = 0; i < 8; i++) {
            uint4 uq = pq[i];
            uint4 uk = pk[i];
            unsigned aq[4] = {uq.x, uq.y, uq.z, uq.w};
            unsigned ak[4] = {uk.x, uk.y, uk.z, uk.w};
            #pragma unroll
            for (int j = 0; j < 4; j++) {
                int c = i * 8 + j * 2;
                float2 fq = h22f2(aq[j]);
                float2 fk = h22f2(ak[j]);
                dq += fq.x * ksc[c] + fq.y * ksc[c+1];
                dk += fk.x * qsc[c] + fk.y * qsc[c+1];
            }
        }
        dq += epsq_s;
        dk += epsk_s;
        float nr = 1.0f / dq, nc = 1.0f / dk;
        nr_s[t] = nr; nc_s[t] = nc;
        g_nrow[nh*L_ + r] = nr;
    }
    __syncthreads();

    // Phase B: thread = (half2-col j, rowgroup g). Re-read (L1/L2 hot), coalesced.
    {
        int j = t & 31, g = t >> 5;     // 32 half2-cols x 8 groups of 32 rows
        const unsigned* pq = (const unsigned*)(g_sq + sbase) + (size_t)r0 * 32;
        const unsigned* pk = (const unsigned*)(g_sk + sbase) + (size_t)r0 * 32;
        float2 qn = make_float2(0.f, 0.f), kn = make_float2(0.f, 0.f);
        #pragma unroll 8
        for (int i = 0; i < 32; i++) {
            int r2 = g * 32 + i;
            float2 fq = h22f2(pq[(size_t)r2 * 32 + j]);
            float2 fk = h22f2(pk[(size_t)r2 * 32 + j]);
            float nr = nr_s[r2], nc = nc_s[r2];
            qn.x += fq.x * nr; qn.y += fq.y * nr;
            kn.x += fk.x * nc; kn.y += fk.y * nc;
        }
        qn_pf[g][2*j] = qn.x; qn_pf[g][2*j+1] = qn.y;
        kn_pf[g][2*j] = kn.x; kn_pf[g][2*j+1] = kn.y;
    }
    __syncthreads();
    if (t < 64) {
        float s = 0.f;
        #pragma unroll
        for (int g = 0; g < 8; g++) s += qn_pf[g][t];
        atomicAdd(&g_qnsum[nh*64 + t], s);
    } else if (t < 128) {
        int c = t - 64;
        float s = 0.f;
        #pragma unroll
        for (int g = 0; g < 8; g++) s += kn_pf[g][c];
        atomicAdd(&g_knsum[nh*64 + c], s);
    }
}

// ---------------- K3: rowfac + cr + per-head max (register dots) ------------
__global__ void __launch_bounds__(256) k3_refine() {
    int nh = blockIdx.x, tile = blockIdx.y;    // 16 tiles x 256 rows
    int t = threadIdx.x;
    const size_t sbase = (size_t)nh * L_ * D_;
    int r0 = tile * 256;

    __shared__ float knc[64], qnc[64];
    __shared__ float epsr_s, epsc_s;
    __shared__ float mx_s[8];

    if (t < 64) {
        knc[t] = g_knsum[nh*64 + t] + EPSF;
        qnc[t] = g_qnsum[nh*64 + t] + EPSF;
    }
    __syncthreads();
    if (t == 0) {
        float a = 0.f, b = 0.f;
        #pragma unroll
        for (int c = 0; c < 64; c++) { a += knc[c]; b += qnc[c]; }
        epsr_s = EPSF * a;
        epsc_s = EPSF * b;
    }
    __syncthreads();

    int r = r0 + t;
    const uint4* pq = (const uint4*)(g_sq + sbase + (size_t)r * D_);
    const uint4* pk = (const uint4*)(g_sk + sbase + (size_t)r * D_);
    float dr = 0.f, dc = 0.f;
    #pragma unroll
    for (int i = 0; i < 8; i++) {
        uint4 uq = pq[i];
        uint4 uk = pk[i];
        unsigned aq[4] = {uq.x, uq.y, uq.z, uq.w};
        unsigned ak[4] = {uk.x, uk.y, uk.z, uk.w};
        #pragma unroll
        for (int j = 0; j < 4; j++) {
            int c = i * 8 + j * 2;
            float2 fq = h22f2(aq[j]);
            float2 fk = h22f2(ak[j]);
            dr += fq.x * knc[c] + fq.y * knc[c+1];
            dc += fk.x * qnc[c] + fk.y * qnc[c+1];
        }
    }
    dr += epsr_s;
    dc += epsc_s;
    // L/S == 1 -> no extra scale on dr
    g_rowfac[nh*L_ + r] = g_nrow[nh*L_ + r] * sigmoidf(dr);
    g_cr[nh*L_ + r] = dc;

    float mx = dc;   // cr strictly positive
    #pragma unroll
    for (int o = 16; o; o >>= 1) mx = fmaxf(mx, __shfl_xor_sync(0xffffffffu, mx, o));
    if ((t & 31) == 0) mx_s[t >> 5] = mx;
    __syncthreads();
    if (t == 0) {
        float m = mx_s[0];
        #pragma unroll
        for (int i = 1; i < 8; i++) m = fmaxf(m, mx_s[i]);
        atomicMax(&g_crmax[nh], __float_as_uint(m));
    }
}

// ---------------- K4: softmax denominator -----------------------------------
__global__ void __launch_bounds__(256) k4_expsum() {
    int nh = blockIdx.x, t = threadIdx.x;
    float mx = __uint_as_float(g_crmax[nh]);
    float s = 0.f;
    int r0 = blockIdx.y * 1024;
    for (int r = r0 + t; r < r0 + 1024; r += 256)
        s += __expf(g_cr[nh*L_ + r] - mx);
    __shared__ float sh[256];
    sh[t] = s;
    __syncthreads();
    for (int o = 128; o; o >>= 1) {
        if (t < o) sh[t] += sh[t + o];
        __syncthreads();
    }
    if (t == 0) atomicAdd(&g_expsum[nh], sh[0]);
}

// ---------------- K5: kv = sk^T @ (w * V), fp16 K path, f32x2 FMA -----------
__global__ void __launch_bounds__(256) k5_kv(const float* __restrict__ V) {
    int nh = blockIdx.x, chunk = blockIdx.y;   // 16 chunks x 256 rows
    int t = threadIdx.x;
    const int base = head_base(nh);
    const size_t sbase = (size_t)nh * L_ * D_;
    int tx = t & 15, ty = t >> 4;
    int e0 = tx * 4, d0 = ty * 4;
    float mx = __uint_as_float(g_crmax[nh]);
    float scale = (float)L_ / g_expsum[nh];
    int r0 = chunk * 256;

    __shared__ __align__(16) float k_sh[16][68];
    __shared__ __align__(16) float v_sh[16][68];
    __shared__ float wgt_s[256];

    wgt_s[t] = __expf(g_cr[nh*L_ + r0 + t] - mx) * scale;

    unsigned long long acc[4][2];
    #pragma unroll
    for (int i = 0; i < 4; i++) { acc[i][0] = 0ull; acc[i][1] = 0ull; }

    int lrow = t >> 4;          // 0..15
    int lj   = t & 15;          // covers 2 half2 (sk) / 4 floats (V)
    __syncthreads();

    for (int rb = 0; rb < 256; rb += 16) {
        __syncthreads();
        int r = r0 + rb + lrow;
        float w = wgt_s[rb + lrow];
        uint2 u2 = *(const uint2*)((const unsigned*)(g_sk + sbase + (size_t)r * D_) + 2*lj);
        float4 v4 = *(const float4*)(V + base + r*RS + 4*lj);
        float2 f0 = h22f2(u2.x), f1 = h22f2(u2.y);
        k_sh[lrow][4*lj]   = f0.x * w;
        k_sh[lrow][4*lj+1] = f0.y * w;
        k_sh[lrow][4*lj+2] = f1.x * w;
        k_sh[lrow][4*lj+3] = f1.y * w;
        *(float4*)&v_sh[lrow][4*lj] = v4;
        __syncthreads();
        #pragma unroll
        for (int s = 0; s < 16; s++) {
            float4 a4 = *(const float4*)&k_sh[s][d0];
            float4 b4 = *(const float4*)&v_sh[s][e0];
            unsigned long long b01 = pk2(b4.x, b4.y);
            unsigned long long b23 = pk2(b4.z, b4.w);
            float a[4] = {a4.x, a4.y, a4.z, a4.w};
            #pragma unroll
            for (int i = 0; i < 4; i++) {
                unsigned long long ai = pk2(a[i], a[i]);
                acc[i][0] = ffma2(ai, b01, acc[i][0]);
                acc[i][1] = ffma2(ai, b23, acc[i][1]);
            }
        }
    }
    #pragma unroll
    for (int i = 0; i < 4; i++) {
        float x0, x1, x2, x3;
        upk2(acc[i][0], x0, x1);
        upk2(acc[i][1], x2, x3);
        float* dst = &g_kv[nh*4096 + (d0+i)*64 + e0];
        atomicAdd(dst+0, x0); atomicAdd(dst+1, x1);
        atomicAdd(dst+2, x2); atomicAdd(dst+3, x3);
    }
}

// ---------------- K6: out = (sq @ kv) * rowfac, fp16 Q path, f32x2 ----------
__global__ void __launch_bounds__(256) k6_out(float* __restrict__ O) {
    int nh = blockIdx.x, chunk = blockIdx.y;   // 64 chunks x 64 rows
    int t = threadIdx.x;
    const int base = head_base(nh);
    const size_t sbase = (size_t)nh * L_ * D_;

    __shared__ __align__(16) float kv_sh[64*64];
    __shared__ float q_sh[64][65];

    for (int i = t * 4; i < 4096; i += 1024)
        *(float4*)&kv_sh[i] = *(const float4*)&g_kv[nh*4096 + i];

    int r0 = chunk * 64;
    // 64 rows x 32 uints = 2048 uints; 256 threads x 8 (2 x uint4)
    {
        const uint4* p = (const uint4*)(g_sq + sbase + (size_t)r0 * D_);
        #pragma unroll
        for (int pass = 0; pass < 2; pass++) {
            int i = t + pass * 256;        // uint4 index, 512 total
            uint4 u = p[i];
            int row = i >> 3, q8 = (i & 7) * 8;
            unsigned a[4] = {u.x, u.y, u.z, u.w};
            #pragma unroll
            for (int j = 0; j < 4; j++) {
                float2 f = h22f2(a[j]);
                q_sh[row][q8 + 2*j]     = f.x;
                q_sh[row][q8 + 2*j + 1] = f.y;
            }
        }
    }
    __syncthreads();

    int tx = t & 15, ty = t >> 4;
    int e0 = tx * 4;
    int rr0 = ty * 4;
    unsigned long long acc[4][2];
    #pragma unroll
    for (int i = 0; i < 4; i++) { acc[i][0] = 0ull; acc[i][1] = 0ull; }
    #pragma unroll 8
    for (int d = 0; d < 64; d++) {
        float4 b4 = *(const float4*)&kv_sh[d*64 + e0];
        unsigned long long b01 = pk2(b4.x, b4.y);
        unsigned long long b23 = pk2(b4.z, b4.w);
        #pragma unroll
        for (int i = 0; i < 4; i++) {
            float a = q_sh[rr0 + i][d];
            unsigned long long ai = pk2(a, a);
            acc[i][0] = ffma2(ai, b01, acc[i][0]);
            acc[i][1] = ffma2(ai, b23, acc[i][1]);
        }
    }
    #pragma unroll
    for (int i = 0; i < 4; i++) {
        int r = r0 + rr0 + i;
        float f = g_rowfac[nh*L_ + r];
        float x0, x1, x2, x3;
        upk2(acc[i][0], x0, x1);
        upk2(acc[i][1], x2, x3);
        float4 o;
        o.x = x0 * f; o.y = x1 * f; o.z = x2 * f; o.w = x3 * f;
        *(float4*)(O + base + r*RS + e0) = o;
    }
}

// ---------------- launch ----------------------------------------------------
extern "C" void kernel_launch(void* const* d_in, const int* in_sizes, int n_in,
                              void* d_out, int out_size) {
    const float* Q = (const float*)d_in[0];
    const float* K = (const float*)d_in[1];
    const float* V = (const float*)d_in[2];
    float* O = (float*)d_out;

    k0_zero   <<<dim3(256),      256>>>();
    k1_sums   <<<dim3(NH, 16),   256>>>(Q, K);
    k2_norm   <<<dim3(NH, 16),   256>>>();
    k3_refine <<<dim3(NH, 16),   256>>>();
    k4_expsum <<<dim3(NH, 4),    256>>>();
    k5_kv     <<<dim3(NH, 16),   256>>>(V);
    k6_out    <<<dim3(NH, 64),   256>>>(O);
}

// round 5
// speedup vs baseline: 1.6827x; 1.0307x over previous
#include <cuda_runtime.h>
#include <cuda_fp16.h>

#define EPSF 1e-6f
#define N_  4
#define L_  4096
#define H_  16
#define D_  64
#define NH  64
#define RS  1024            /* row stride in floats = H*D */
#define PER_N (L_*H_*D_)

// ---------------- scratch (device globals; no allocation allowed) ----------
// per-(head,chunk) partials — fully overwritten each run, no zeroing needed
__device__ float g_qsum_p [NH*16*64];
__device__ float g_ksum_p [NH*16*64];
__device__ float g_qnsum_p[NH*16*64];
__device__ float g_knsum_p[NH*16*64];
__device__ float g_crmax_p[NH*16];
__device__ float g_nrow  [NH*L_];
__device__ float g_rowfac[NH*L_];
__device__ float g_cr    [NH*L_];    // after k4: holds softmax weights
__device__ float g_kv    [NH*D_*D_]; // zeroed in k4, accumulated in k5
// fp16 sigmoid scratch: [nh][L][64] contiguous (32 MiB each)
__device__ __align__(16) __half g_sq[(size_t)NH*L_*D_];
__device__ __align__(16) __half g_sk[(size_t)NH*L_*D_];

__device__ __forceinline__ float sigmoidf(float x) {
    float t;
    asm("tanh.approx.f32 %0, %1;" : "=f"(t) : "f"(0.5f * x));
    return fmaf(0.5f, t, 0.5f);
}
__device__ __forceinline__ int head_base(int nh) {
    int n = nh >> 4, h = nh & 15;
    return n * PER_N + h * D_;
}
__device__ __forceinline__ float2 h22f2(unsigned u) {
    return __half22float2(*reinterpret_cast<__half2*>(&u));
}

// f32x2 packed-FMA helpers (sm_10x)
__device__ __forceinline__ unsigned long long pk2(float x, float y) {
    unsigned long long r;
    asm("mov.b64 %0, {%1, %2};" : "=l"(r) : "f"(x), "f"(y));
    return r;
}
__device__ __forceinline__ void upk2(unsigned long long v, float& x, float& y) {
    asm("mov.b64 {%0, %1}, %2;" : "=f"(x), "=f"(y) : "l"(v));
}
__device__ __forceinline__ unsigned long long ffma2(unsigned long long a,
                                                    unsigned long long b,
                                                    unsigned long long c) {
    unsigned long long d;
    asm("fma.rn.f32x2 %0, %1, %2, %3;" : "=l"(d) : "l"(a), "l"(b), "l"(c));
    return d;
}

struct __align__(8) H4 { __half2 a, b; };

// ---------------- K1: sigmoid -> fp16 scratch + column-sum partials ---------
__global__ void __launch_bounds__(256) k1_sums(const float* __restrict__ Q,
                                               const float* __restrict__ K) {
    int nh = blockIdx.x, chunk = blockIdx.y;   // 16 chunks of 256 rows
    int t = threadIdx.x;
    int col = (t & 15) * 4;
    int rg  = t >> 4;
    const int base = head_base(nh);
    const size_t sbase = (size_t)nh * L_ * D_;
    float qs[4] = {}, ks[4] = {};
    int r0 = chunk * 256;
    #pragma unroll
    for (int ob = 0; ob < 4; ob++) {
        // batch 8 independent loads (4 Q + 4 K rows)
        float4 q[4], k[4];
        #pragma unroll
        for (int i = 0; i < 4; i++) {
            int r = r0 + ob * 64 + i * 16 + rg;
            int off = base + r * RS + col;
            q[i] = *(const float4*)(Q + off);
        }
        #pragma unroll
        for (int i = 0; i < 4; i++) {
            int r = r0 + ob * 64 + i * 16 + rg;
            int off = base + r * RS + col;
            k[i] = *(const float4*)(K + off);
        }
        #pragma unroll
        for (int i = 0; i < 4; i++) {
            int r = r0 + ob * 64 + i * 16 + rg;
            float sq0 = sigmoidf(q[i].x), sq1 = sigmoidf(q[i].y);
            float sq2 = sigmoidf(q[i].z), sq3 = sigmoidf(q[i].w);
            float sk0 = sigmoidf(k[i].x), sk1 = sigmoidf(k[i].y);
            float sk2 = sigmoidf(k[i].z), sk3 = sigmoidf(k[i].w);
            qs[0] += sq0; qs[1] += sq1; qs[2] += sq2; qs[3] += sq3;
            ks[0] += sk0; ks[1] += sk1; ks[2] += sk2; ks[3] += sk3;
            H4 hq; hq.a = __floats2half2_rn(sq0, sq1); hq.b = __floats2half2_rn(sq2, sq3);
            H4 hk; hk.a = __floats2half2_rn(sk0, sk1); hk.b = __floats2half2_rn(sk2, sk3);
            size_t sidx = sbase + (size_t)r * D_ + col;
            *(H4*)(g_sq + sidx) = hq;
            *(H4*)(g_sk + sidx) = hk;
        }
    }
    __shared__ float qsum_s[64], ksum_s[64];
    if (t < 64) { qsum_s[t] = 0.f; ksum_s[t] = 0.f; }
    __syncthreads();
    #pragma unroll
    for (int i = 0; i < 4; i++) {
        atomicAdd(&qsum_s[col + i], qs[i]);
        atomicAdd(&ksum_s[col + i], ks[i]);
    }
    __syncthreads();
    if (t < 64) {
        g_qsum_p[(nh*16 + chunk)*64 + t] = qsum_s[t];
        g_ksum_p[(nh*16 + chunk)*64 + t] = ksum_s[t];
    }
}

// ---------------- K2: nrow + qn/kn partials (batched register dots) ---------
__global__ void __launch_bounds__(256) k2_norm() {
    int nh = blockIdx.x, tile = blockIdx.y;    // 16 tiles x 256 rows
    int t = threadIdx.x;
    const size_t sbase = (size_t)nh * L_ * D_;
    int r0 = tile * 256;

    __shared__ float ksc[64], qsc[64];
    __shared__ float nr_s[256], nc_s[256];
    __shared__ float qn_pf[8][66], kn_pf[8][66];
    __shared__ float epsq_s, epsk_s;

    if (t < 64) {
        float a = 0.f, b = 0.f;
        #pragma unroll
        for (int c = 0; c < 16; c++) {
            a += g_ksum_p[(nh*16 + c)*64 + t];
            b += g_qsum_p[(nh*16 + c)*64 + t];
        }
        ksc[t] = a + EPSF;
        qsc[t] = b + EPSF;
    }
    __syncthreads();
    if (t == 0) {
        float a = 0.f, b = 0.f;
        #pragma unroll
        for (int c = 0; c < 64; c++) { a += ksc[c]; b += qsc[c]; }
        epsq_s = EPSF * a;
        epsk_s = EPSF * b;
    }
    __syncthreads();

    // Phase A: thread = row; front-batched loads for max MLP
    {
        int r = r0 + t;
        const uint4* pq = (const uint4*)(g_sq + sbase + (size_t)r * D_);
        const uint4* pk = (const uint4*)(g_sk + sbase + (size_t)r * D_);
        uint4 rq[8], rk[8];
        #pragma unroll
        for (int i = 0; i < 8; i++) rq[i] = pq[i];
        #pragma unroll
        for (int i = 0; i < 8; i++) rk[i] = pk[i];
        float dq = 0.f, dk = 0.f;
        #pragma unroll
        for (int i = 0; i < 8; i++) {
            unsigned aq[4] = {rq[i].x, rq[i].y, rq[i].z, rq[i].w};
            unsigned ak[4] = {rk[i].x, rk[i].y, rk[i].z, rk[i].w};
            #pragma unroll
            for (int j = 0; j < 4; j++) {
                int c = i * 8 + j * 2;
                float2 fq = h22f2(aq[j]);
                float2 fk = h22f2(ak[j]);
                dq += fq.x * ksc[c] + fq.y * ksc[c+1];
                dk += fk.x * qsc[c] + fk.y * qsc[c+1];
            }
        }
        dq += epsq_s;
        dk += epsk_s;
        float nr = 1.0f / dq, nc = 1.0f / dk;
        nr_s[t] = nr; nc_s[t] = nc;
        g_nrow[nh*L_ + r] = nr;
    }
    __syncthreads();

    // Phase B: column sums (re-read L1-hot lines, coalesced per warp)
    {
        int j = t & 31, g = t >> 5;
        const unsigned* pq = (const unsigned*)(g_sq + sbase) + (size_t)r0 * 32;
        const unsigned* pk = (const unsigned*)(g_sk + sbase) + (size_t)r0 * 32;
        float2 qn = make_float2(0.f, 0.f), kn = make_float2(0.f, 0.f);
        #pragma unroll 8
        for (int i = 0; i < 32; i++) {
            int r2 = g * 32 + i;
            float2 fq = h22f2(pq[(size_t)r2 * 32 + j]);
            float2 fk = h22f2(pk[(size_t)r2 * 32 + j]);
            float nr = nr_s[r2], nc = nc_s[r2];
            qn.x += fq.x * nr; qn.y += fq.y * nr;
            kn.x += fk.x * nc; kn.y += fk.y * nc;
        }
        qn_pf[g][2*j] = qn.x; qn_pf[g][2*j+1] = qn.y;
        kn_pf[g][2*j] = kn.x; kn_pf[g][2*j+1] = kn.y;
    }
    __syncthreads();
    if (t < 64) {
        float s = 0.f;
        #pragma unroll
        for (int g = 0; g < 8; g++) s += qn_pf[g][t];
        g_qnsum_p[(nh*16 + tile)*64 + t] = s;
    } else if (t < 128) {
        int c = t - 64;
        float s = 0.f;
        #pragma unroll
        for (int g = 0; g < 8; g++) s += kn_pf[g][c];
        g_knsum_p[(nh*16 + tile)*64 + c] = s;
    }
}

// ---------------- K3: rowfac + cr + per-tile max (batched register dots) ----
__global__ void __launch_bounds__(256) k3_refine() {
    int nh = blockIdx.x, tile = blockIdx.y;    // 16 tiles x 256 rows
    int t = threadIdx.x;
    const size_t sbase = (size_t)nh * L_ * D_;
    int r0 = tile * 256;

    __shared__ float knc[64], qnc[64];
    __shared__ float epsr_s, epsc_s;
    __shared__ float mx_s[8];

    if (t < 64) {
        float a = 0.f, b = 0.f;
        #pragma unroll
        for (int c = 0; c < 16; c++) {
            a += g_knsum_p[(nh*16 + c)*64 + t];
            b += g_qnsum_p[(nh*16 + c)*64 + t];
        }
        knc[t] = a + EPSF;
        qnc[t] = b + EPSF;
    }
    __syncthreads();
    if (t == 0) {
        float a = 0.f, b = 0.f;
        #pragma unroll
        for (int c = 0; c < 64; c++) { a += knc[c]; b += qnc[c]; }
        epsr_s = EPSF * a;
        epsc_s = EPSF * b;
    }
    __syncthreads();

    int r = r0 + t;
    const uint4* pq = (const uint4*)(g_sq + sbase + (size_t)r * D_);
    const uint4* pk = (const uint4*)(g_sk + sbase + (size_t)r * D_);
    uint4 rq[8], rk[8];
    #pragma unroll
    for (int i = 0; i < 8; i++) rq[i] = pq[i];
    #pragma unroll
    for (int i = 0; i < 8; i++) rk[i] = pk[i];
    float dr = 0.f, dc = 0.f;
    #pragma unroll
    for (int i = 0; i < 8; i++) {
        unsigned aq[4] = {rq[i].x, rq[i].y, rq[i].z, rq[i].w};
        unsigned ak[4] = {rk[i].x, rk[i].y, rk[i].z, rk[i].w};
        #pragma unroll
        for (int j = 0; j < 4; j++) {
            int c = i * 8 + j * 2;
            float2 fq = h22f2(aq[j]);
            float2 fk = h22f2(ak[j]);
            dr += fq.x * knc[c] + fq.y * knc[c+1];
            dc += fk.x * qnc[c] + fk.y * qnc[c+1];
        }
    }
    dr += epsr_s;
    dc += epsc_s;
    // L/S == 1 -> no extra scale on dr
    g_rowfac[nh*L_ + r] = g_nrow[nh*L_ + r] * sigmoidf(dr);
    g_cr[nh*L_ + r] = dc;

    float mx = dc;   // cr strictly positive
    #pragma unroll
    for (int o = 16; o; o >>= 1) mx = fmaxf(mx, __shfl_xor_sync(0xffffffffu, mx, o));
    if ((t & 31) == 0) mx_s[t >> 5] = mx;
    __syncthreads();
    if (t == 0) {
        float m = mx_s[0];
        #pragma unroll
        for (int i = 1; i < 8; i++) m = fmaxf(m, mx_s[i]);
        g_crmax_p[nh*16 + tile] = m;
    }
}

// ---------------- K4: softmax weights in place + zero kv --------------------
__global__ void __launch_bounds__(256) k4_weights() {
    int nh = blockIdx.x, t = threadIdx.x;
    __shared__ float mx_sh;
    __shared__ float red[256];

    if (t < 32) {
        float v = (t < 16) ? g_crmax_p[nh*16 + t] : -1e30f;
        #pragma unroll
        for (int o = 8; o; o >>= 1) v = fmaxf(v, __shfl_xor_sync(0xffffffffu, v, o));
        if (t == 0) mx_sh = v;
    }
    // zero kv slice for this head (runs before k5)
    float4 z = make_float4(0.f, 0.f, 0.f, 0.f);
    #pragma unroll
    for (int j = 0; j < 4; j++)
        *(float4*)&g_kv[nh*4096 + t*4 + j*1024] = z;
    __syncthreads();
    float mx = mx_sh;

    float4* pc = (float4*)(g_cr + nh*L_);
    float4 a[4];
    #pragma unroll
    for (int j = 0; j < 4; j++) a[j] = pc[t + j*256];
    float e[16];
    #pragma unroll
    for (int j = 0; j < 4; j++) {
        e[4*j+0] = __expf(a[j].x - mx);
        e[4*j+1] = __expf(a[j].y - mx);
        e[4*j+2] = __expf(a[j].z - mx);
        e[4*j+3] = __expf(a[j].w - mx);
    }
    float s = 0.f;
    #pragma unroll
    for (int i = 0; i < 16; i++) s += e[i];
    red[t] = s;
    __syncthreads();
    for (int o = 128; o; o >>= 1) {
        if (t < o) red[t] += red[t + o];
        __syncthreads();
    }
    float scale = (float)L_ / red[0];
    #pragma unroll
    for (int j = 0; j < 4; j++) {
        float4 w;
        w.x = e[4*j+0] * scale; w.y = e[4*j+1] * scale;
        w.z = e[4*j+2] * scale; w.w = e[4*j+3] * scale;
        pc[t + j*256] = w;   // g_cr now holds weights
    }
}

// ---------------- K5: kv = sk^T @ (w*V), double-buffered, f32x2 -------------
__global__ void __launch_bounds__(256) k5_kv(const float* __restrict__ V) {
    int nh = blockIdx.x, chunk = blockIdx.y;   // 16 chunks x 256 rows
    int t = threadIdx.x;
    const int base = head_base(nh);
    const size_t sbase = (size_t)nh * L_ * D_;
    int tx = t & 15, ty = t >> 4;
    int e0 = tx * 4, d0 = ty * 4;
    int r0 = chunk * 256;
    int lrow = t >> 4;          // 0..15
    int lj   = t & 15;

    __shared__ __align__(16) float k_sh[2][16][68];
    __shared__ __align__(16) float v_sh[2][16][68];

    unsigned long long acc[4][2];
    #pragma unroll
    for (int i = 0; i < 4; i++) { acc[i][0] = 0ull; acc[i][1] = 0ull; }

    uint2 u2; float4 v4; float w;
    {   // prologue: stage 0
        int r = r0 + lrow;
        u2 = *(const uint2*)((const unsigned*)(g_sk + sbase + (size_t)r * D_) + 2*lj);
        v4 = *(const float4*)(V + base + r*RS + 4*lj);
        w  = g_cr[nh*L_ + r];
        float2 f0 = h22f2(u2.x), f1 = h22f2(u2.y);
        k_sh[0][lrow][4*lj]   = f0.x * w;
        k_sh[0][lrow][4*lj+1] = f0.y * w;
        k_sh[0][lrow][4*lj+2] = f1.x * w;
        k_sh[0][lrow][4*lj+3] = f1.y * w;
        *(float4*)&v_sh[0][lrow][4*lj] = v4;
    }
    __syncthreads();

    for (int stg = 0; stg < 16; stg++) {
        int cur = stg & 1;
        uint2 nu2; float4 nv4; float nw = 0.f;
        if (stg < 15) {   // prefetch next stage into registers
            int r = r0 + (stg + 1) * 16 + lrow;
            nu2 = *(const uint2*)((const unsigned*)(g_sk + sbase + (size_t)r * D_) + 2*lj);
            nv4 = *(const float4*)(V + base + r*RS + 4*lj);
            nw  = g_cr[nh*L_ + r];
        }
        #pragma unroll
        for (int s = 0; s < 16; s++) {
            float4 a4 = *(const float4*)&k_sh[cur][s][d0];
            float4 b4 = *(const float4*)&v_sh[cur][s][e0];
            unsigned long long b01 = pk2(b4.x, b4.y);
            unsigned long long b23 = pk2(b4.z, b4.w);
            float a[4] = {a4.x, a4.y, a4.z, a4.w};
            #pragma unroll
            for (int i = 0; i < 4; i++) {
                unsigned long long ai = pk2(a[i], a[i]);
                acc[i][0] = ffma2(ai, b01, acc[i][0]);
                acc[i][1] = ffma2(ai, b23, acc[i][1]);
            }
        }
        __syncthreads();
        if (stg < 15) {
            float2 f0 = h22f2(nu2.x), f1 = h22f2(nu2.y);
            k_sh[cur^1][lrow][4*lj]   = f0.x * nw;
            k_sh[cur^1][lrow][4*lj+1] = f0.y * nw;
            k_sh[cur^1][lrow][4*lj+2] = f1.x * nw;
            k_sh[cur^1][lrow][4*lj+3] = f1.y * nw;
            *(float4*)&v_sh[cur^1][lrow][4*lj] = nv4;
        }
        __syncthreads();
    }
    #pragma unroll
    for (int i = 0; i < 4; i++) {
        float x0, x1, x2, x3;
        upk2(acc[i][0], x0, x1);
        upk2(acc[i][1], x2, x3);
        float* dst = &g_kv[nh*4096 + (d0+i)*64 + e0];
        atomicAdd(dst+0, x0); atomicAdd(dst+1, x1);
        atomicAdd(dst+2, x2); atomicAdd(dst+3, x3);
    }
}

// ---------------- K6: out = (sq @ kv) * rowfac, f32x2 -----------------------
__global__ void __launch_bounds__(256) k6_out(float* __restrict__ O) {
    int nh = blockIdx.x, chunk = blockIdx.y;   // 64 chunks x 64 rows
    int t = threadIdx.x;
    const int base = head_base(nh);
    const size_t sbase = (size_t)nh * L_ * D_;

    __shared__ __align__(16) float kv_sh[64*64];
    __shared__ float q_sh[64][65];

    // batched kv load (4 independent float4)
    {
        const float4* p = (const float4*)&g_kv[nh*4096];
        float4 kvreg[4];
        #pragma unroll
        for (int j = 0; j < 4; j++) kvreg[j] = p[t + j*256];
        #pragma unroll
        for (int j = 0; j < 4; j++) *(float4*)&kv_sh[(t + j*256)*4] = kvreg[j];
    }
    int r0 = chunk * 64;
    {
        const uint4* p = (const uint4*)(g_sq + sbase + (size_t)r0 * D_);
        uint4 u[2];
        #pragma unroll
        for (int pass = 0; pass < 2; pass++) u[pass] = p[t + pass*256];
        #pragma unroll
        for (int pass = 0; pass < 2; pass++) {
            int i = t + pass * 256;
            int row = i >> 3, q8 = (i & 7) * 8;
            unsigned a[4] = {u[pass].x, u[pass].y, u[pass].z, u[pass].w};
            #pragma unroll
            for (int j = 0; j < 4; j++) {
                float2 f = h22f2(a[j]);
                q_sh[row][q8 + 2*j]     = f.x;
                q_sh[row][q8 + 2*j + 1] = f.y;
            }
        }
    }
    __syncthreads();

    int tx = t & 15, ty = t >> 4;
    int e0 = tx * 4;
    int rr0 = ty * 4;
    unsigned long long acc[4][2];
    #pragma unroll
    for (int i = 0; i < 4; i++) { acc[i][0] = 0ull; acc[i][1] = 0ull; }
    #pragma unroll 8
    for (int d = 0; d < 64; d++) {
        float4 b4 = *(const float4*)&kv_sh[d*64 + e0];
        unsigned long long b01 = pk2(b4.x, b4.y);
        unsigned long long b23 = pk2(b4.z, b4.w);
        #pragma unroll
        for (int i = 0; i < 4; i++) {
            float a = q_sh[rr0 + i][d];
            unsigned long long ai = pk2(a, a);
            acc[i][0] = ffma2(ai, b01, acc[i][0]);
            acc[i][1] = ffma2(ai, b23, acc[i][1]);
        }
    }
    #pragma unroll
    for (int i = 0; i < 4; i++) {
        int r = r0 + rr0 + i;
        float f = g_rowfac[nh*L_ + r];
        float x0, x1, x2, x3;
        upk2(acc[i][0], x0, x1);
        upk2(acc[i][1], x2, x3);
        float4 o;
        o.x = x0 * f; o.y = x1 * f; o.z = x2 * f; o.w = x3 * f;
        *(float4*)(O + base + r*RS + e0) = o;
    }
}

// ---------------- launch ----------------------------------------------------
extern "C" void kernel_launch(void* const* d_in, const int* in_sizes, int n_in,
                              void* d_out, int out_size) {
    const float* Q = (const float*)d_in[0];
    const float* K = (const float*)d_in[1];
    const float* V = (const float*)d_in[2];
    float* O = (float*)d_out;

    k1_sums   <<<dim3(NH, 16), 256>>>(Q, K);
    k2_norm   <<<dim3(NH, 16), 256>>>();
    k3_refine <<<dim3(NH, 16), 256>>>();
    k4_weights<<<dim3(NH),     256>>>();
    k5_kv     <<<dim3(NH, 16), 256>>>(V);
    k6_out    <<<dim3(NH, 64), 256>>>(O);
}

// round 6
// speedup vs baseline: 2.8991x; 1.7229x over previous
#include <cuda_runtime.h>
#include <cuda_fp16.h>

#define EPSF 1e-6f
#define N_  4
#define L_  4096
#define H_  16
#define D_  64
#define NH  64
#define RS  1024            /* row stride in floats = H*D */
#define PER_N (L_*H_*D_)

// ---------------- scratch (device globals; no allocation allowed) ----------
__device__ float g_qsum_p [NH*16*64];
__device__ float g_ksum_p [NH*16*64];
__device__ float g_qnsum_p[NH*16*64];
__device__ float g_knsum_p[NH*16*64];
__device__ float g_crmax_p[NH*16];
__device__ float g_nrow  [NH*L_];
__device__ float g_rowfac[NH*L_];
__device__ float g_cr    [NH*L_];    // after k4: holds softmax weights
__device__ float g_kv    [NH*D_*D_]; // zeroed in k4, accumulated in k5
__device__ __align__(16) __half g_sq[(size_t)NH*L_*D_];
__device__ __align__(16) __half g_sk[(size_t)NH*L_*D_];

__device__ __forceinline__ float sigmoidf(float x) {
    float t;
    asm("tanh.approx.f32 %0, %1;" : "=f"(t) : "f"(0.5f * x));
    return fmaf(0.5f, t, 0.5f);
}
__device__ __forceinline__ int head_base(int nh) {
    int n = nh >> 4, h = nh & 15;
    return n * PER_N + h * D_;
}
__device__ __forceinline__ float2 h22f2(unsigned u) {
    return __half22float2(*reinterpret_cast<__half2*>(&u));
}
__device__ __forceinline__ void mma16816(float& c0, float& c1, float& c2, float& c3,
                                         unsigned a0, unsigned a1, unsigned a2, unsigned a3,
                                         unsigned b0, unsigned b1) {
    asm volatile(
        "mma.sync.aligned.m16n8k16.row.col.f32.f16.f16.f32 "
        "{%0,%1,%2,%3}, {%4,%5,%6,%7}, {%8,%9}, {%0,%1,%2,%3};"
        : "+f"(c0), "+f"(c1), "+f"(c2), "+f"(c3)
        : "r"(a0), "r"(a1), "r"(a2), "r"(a3), "r"(b0), "r"(b1));
}

struct __align__(8) H4 { __half2 a, b; };

// ---------------- K1: sigmoid -> fp16 scratch + column-sum partials ---------
__global__ void __launch_bounds__(256) k1_sums(const float* __restrict__ Q,
                                               const float* __restrict__ K) {
    int nh = blockIdx.x, chunk = blockIdx.y;
    int t = threadIdx.x;
    int col = (t & 15) * 4;
    int rg  = t >> 4;
    const int base = head_base(nh);
    const size_t sbase = (size_t)nh * L_ * D_;
    float qs[4] = {}, ks[4] = {};
    int r0 = chunk * 256;
    #pragma unroll
    for (int ob = 0; ob < 4; ob++) {
        float4 q[4], k[4];
        #pragma unroll
        for (int i = 0; i < 4; i++) {
            int r = r0 + ob * 64 + i * 16 + rg;
            q[i] = *(const float4*)(Q + base + r * RS + col);
        }
        #pragma unroll
        for (int i = 0; i < 4; i++) {
            int r = r0 + ob * 64 + i * 16 + rg;
            k[i] = *(const float4*)(K + base + r * RS + col);
        }
        #pragma unroll
        for (int i = 0; i < 4; i++) {
            int r = r0 + ob * 64 + i * 16 + rg;
            float sq0 = sigmoidf(q[i].x), sq1 = sigmoidf(q[i].y);
            float sq2 = sigmoidf(q[i].z), sq3 = sigmoidf(q[i].w);
            float sk0 = sigmoidf(k[i].x), sk1 = sigmoidf(k[i].y);
            float sk2 = sigmoidf(k[i].z), sk3 = sigmoidf(k[i].w);
            qs[0] += sq0; qs[1] += sq1; qs[2] += sq2; qs[3] += sq3;
            ks[0] += sk0; ks[1] += sk1; ks[2] += sk2; ks[3] += sk3;
            H4 hq; hq.a = __floats2half2_rn(sq0, sq1); hq.b = __floats2half2_rn(sq2, sq3);
            H4 hk; hk.a = __floats2half2_rn(sk0, sk1); hk.b = __floats2half2_rn(sk2, sk3);
            size_t sidx = sbase + (size_t)r * D_ + col;
            *(H4*)(g_sq + sidx) = hq;
            *(H4*)(g_sk + sidx) = hk;
        }
    }
    __shared__ float qsum_s[64], ksum_s[64];
    if (t < 64) { qsum_s[t] = 0.f; ksum_s[t] = 0.f; }
    __syncthreads();
    #pragma unroll
    for (int i = 0; i < 4; i++) {
        atomicAdd(&qsum_s[col + i], qs[i]);
        atomicAdd(&ksum_s[col + i], ks[i]);
    }
    __syncthreads();
    if (t < 64) {
        g_qsum_p[(nh*16 + chunk)*64 + t] = qsum_s[t];
        g_ksum_p[(nh*16 + chunk)*64 + t] = ksum_s[t];
    }
}

// ---------------- K2: nrow + qn/kn partials, single pass, 8 thr/row ---------
__global__ void __launch_bounds__(256) k2_norm() {
    int nh = blockIdx.x, tile = blockIdx.y;    // 16 tiles x 256 rows
    int t = threadIdx.x;
    const size_t sbase = (size_t)nh * L_ * D_;
    int r0 = tile * 256;

    __shared__ float ksc[64], qsc[64];
    __shared__ float qn_pf[8][68], kn_pf[8][68];
    __shared__ float eps_q, eps_k;

    if (t < 64) {
        float a = 0.f, b = 0.f;
        #pragma unroll
        for (int c = 0; c < 16; c++) {
            a += g_ksum_p[(nh*16 + c)*64 + t];
            b += g_qsum_p[(nh*16 + c)*64 + t];
        }
        ksc[t] = a + EPSF;
        qsc[t] = b + EPSF;
    }
    __syncthreads();
    if (t == 0) {
        float a = 0.f, b = 0.f;
        #pragma unroll
        for (int c = 0; c < 64; c++) { a += ksc[c]; b += qsc[c]; }
        eps_q = EPSF * a;
        eps_k = EPSF * b;
    }
    __syncthreads();

    int sub = t & 7, grp = t >> 3;             // 32 row-groups
    float ksr[8], qsr[8];
    #pragma unroll
    for (int j = 0; j < 8; j++) { ksr[j] = ksc[sub*8 + j]; qsr[j] = qsc[sub*8 + j]; }
    float epq = eps_q, epk = eps_k;

    const uint4* pq = (const uint4*)(g_sq + sbase);
    const uint4* pk = (const uint4*)(g_sk + sbase);
    float qn[8] = {}, kn[8] = {};

    #pragma unroll
    for (int pp = 0; pp < 4; pp++) {
        int rA = r0 + (pp*2)*32 + grp;
        int rB = rA + 32;
        uint4 uqA = pq[rA*8 + sub];
        uint4 ukA = pk[rA*8 + sub];
        uint4 uqB = pq[rB*8 + sub];
        uint4 ukB = pk[rB*8 + sub];
        #pragma unroll
        for (int half = 0; half < 2; half++) {
            uint4 uq = half ? uqB : uqA;
            uint4 uk = half ? ukB : ukA;
            int r = half ? rB : rA;
            unsigned wq[4] = {uq.x, uq.y, uq.z, uq.w};
            unsigned wk[4] = {uk.x, uk.y, uk.z, uk.w};
            float fq[8], fk[8];
            #pragma unroll
            for (int j = 0; j < 4; j++) {
                float2 a = h22f2(wq[j]); fq[2*j] = a.x; fq[2*j+1] = a.y;
                float2 b = h22f2(wk[j]); fk[2*j] = b.x; fk[2*j+1] = b.y;
            }
            float dq = 0.f, dk = 0.f;
            #pragma unroll
            for (int j = 0; j < 8; j++) { dq += fq[j]*ksr[j]; dk += fk[j]*qsr[j]; }
            #pragma unroll
            for (int o = 1; o < 8; o <<= 1) {
                dq += __shfl_xor_sync(0xffffffffu, dq, o);
                dk += __shfl_xor_sync(0xffffffffu, dk, o);
            }
            dq += epq; dk += epk;
            float nr = 1.0f / dq, nc = 1.0f / dk;
            if (sub == 0) g_nrow[nh*L_ + r] = nr;
            #pragma unroll
            for (int j = 0; j < 8; j++) { qn[j] += fq[j]*nr; kn[j] += fk[j]*nc; }
        }
    }
    // reduce 4 row-groups within warp (lanes stride 8)
    #pragma unroll
    for (int o = 8; o <= 16; o <<= 1) {
        #pragma unroll
        for (int j = 0; j < 8; j++) {
            qn[j] += __shfl_xor_sync(0xffffffffu, qn[j], o);
            kn[j] += __shfl_xor_sync(0xffffffffu, kn[j], o);
        }
    }
    if ((t & 31) < 8) {
        int w = t >> 5;
        #pragma unroll
        for (int j = 0; j < 8; j++) {
            qn_pf[w][sub*8 + j] = qn[j];
            kn_pf[w][sub*8 + j] = kn[j];
        }
    }
    __syncthreads();
    if (t < 64) {
        float s = 0.f;
        #pragma unroll
        for (int w = 0; w < 8; w++) s += qn_pf[w][t];
        g_qnsum_p[(nh*16 + tile)*64 + t] = s;
    } else if (t < 128) {
        int c = t - 64;
        float s = 0.f;
        #pragma unroll
        for (int w = 0; w < 8; w++) s += kn_pf[w][c];
        g_knsum_p[(nh*16 + tile)*64 + c] = s;
    }
}

// ---------------- K3: rowfac + cr + per-tile max, 8 thr/row -----------------
__global__ void __launch_bounds__(256) k3_refine() {
    int nh = blockIdx.x, tile = blockIdx.y;
    int t = threadIdx.x;
    const size_t sbase = (size_t)nh * L_ * D_;
    int r0 = tile * 256;

    __shared__ float knc[64], qnc[64];
    __shared__ float eps_r, eps_c;
    __shared__ float mx_s[8];

    if (t < 64) {
        float a = 0.f, b = 0.f;
        #pragma unroll
        for (int c = 0; c < 16; c++) {
            a += g_knsum_p[(nh*16 + c)*64 + t];
            b += g_qnsum_p[(nh*16 + c)*64 + t];
        }
        knc[t] = a + EPSF;
        qnc[t] = b + EPSF;
    }
    __syncthreads();
    if (t == 0) {
        float a = 0.f, b = 0.f;
        #pragma unroll
        for (int c = 0; c < 64; c++) { a += knc[c]; b += qnc[c]; }
        eps_r = EPSF * a;
        eps_c = EPSF * b;
    }
    __syncthreads();

    int sub = t & 7, grp = t >> 3;
    float knr[8], qnr[8];
    #pragma unroll
    for (int j = 0; j < 8; j++) { knr[j] = knc[sub*8 + j]; qnr[j] = qnc[sub*8 + j]; }
    float epr = eps_r, epc = eps_c;

    const uint4* pq = (const uint4*)(g_sq + sbase);
    const uint4* pk = (const uint4*)(g_sk + sbase);
    float mx = 0.f;   // cr strictly positive

    #pragma unroll
    for (int pp = 0; pp < 4; pp++) {
        int rA = r0 + (pp*2)*32 + grp;
        int rB = rA + 32;
        uint4 uqA = pq[rA*8 + sub];
        uint4 ukA = pk[rA*8 + sub];
        uint4 uqB = pq[rB*8 + sub];
        uint4 ukB = pk[rB*8 + sub];
        #pragma unroll
        for (int half = 0; half < 2; half++) {
            uint4 uq = half ? uqB : uqA;
            uint4 uk = half ? ukB : ukA;
            int r = half ? rB : rA;
            unsigned wq[4] = {uq.x, uq.y, uq.z, uq.w};
            unsigned wk[4] = {uk.x, uk.y, uk.z, uk.w};
            float dr = 0.f, dc = 0.f;
            #pragma unroll
            for (int j = 0; j < 4; j++) {
                float2 a = h22f2(wq[j]);
                float2 b = h22f2(wk[j]);
                dr += a.x*knr[2*j] + a.y*knr[2*j+1];
                dc += b.x*qnr[2*j] + b.y*qnr[2*j+1];
            }
            #pragma unroll
            for (int o = 1; o < 8; o <<= 1) {
                dr += __shfl_xor_sync(0xffffffffu, dr, o);
                dc += __shfl_xor_sync(0xffffffffu, dc, o);
            }
            dr += epr; dc += epc;
            if (sub == 0) {
                g_rowfac[nh*L_ + r] = g_nrow[nh*L_ + r] * sigmoidf(dr);
                g_cr[nh*L_ + r] = dc;
            }
            mx = fmaxf(mx, dc);
        }
    }
    #pragma unroll
    for (int o = 16; o; o >>= 1) mx = fmaxf(mx, __shfl_xor_sync(0xffffffffu, mx, o));
    if ((t & 31) == 0) mx_s[t >> 5] = mx;
    __syncthreads();
    if (t == 0) {
        float m = mx_s[0];
        #pragma unroll
        for (int i = 1; i < 8; i++) m = fmaxf(m, mx_s[i]);
        g_crmax_p[nh*16 + tile] = m;
    }
}

// ---------------- K4: softmax weights in place + zero kv --------------------
__global__ void __launch_bounds__(256) k4_weights() {
    int nh = blockIdx.x, t = threadIdx.x;
    __shared__ float mx_sh;
    __shared__ float red[256];

    if (t < 32) {
        float v = (t < 16) ? g_crmax_p[nh*16 + t] : -1e30f;
        #pragma unroll
        for (int o = 8; o; o >>= 1) v = fmaxf(v, __shfl_xor_sync(0xffffffffu, v, o));
        if (t == 0) mx_sh = v;
    }
    float4 z = make_float4(0.f, 0.f, 0.f, 0.f);
    #pragma unroll
    for (int j = 0; j < 4; j++)
        *(float4*)&g_kv[nh*4096 + t*4 + j*1024] = z;
    __syncthreads();
    float mx = mx_sh;

    float4* pc = (float4*)(g_cr + nh*L_);
    float4 a[4];
    #pragma unroll
    for (int j = 0; j < 4; j++) a[j] = pc[t + j*256];
    float e[16];
    #pragma unroll
    for (int j = 0; j < 4; j++) {
        e[4*j+0] = __expf(a[j].x - mx);
        e[4*j+1] = __expf(a[j].y - mx);
        e[4*j+2] = __expf(a[j].z - mx);
        e[4*j+3] = __expf(a[j].w - mx);
    }
    float s = 0.f;
    #pragma unroll
    for (int i = 0; i < 16; i++) s += e[i];
    red[t] = s;
    __syncthreads();
    for (int o = 128; o; o >>= 1) {
        if (t < o) red[t] += red[t + o];
        __syncthreads();
    }
    float scale = (float)L_ / red[0];
    #pragma unroll
    for (int j = 0; j < 4; j++) {
        float4 w;
        w.x = e[4*j+0] * scale; w.y = e[4*j+1] * scale;
        w.z = e[4*j+2] * scale; w.w = e[4*j+3] * scale;
        pc[t + j*256] = w;
    }
}

// ---------------- K5: kv += (w*sk)^T @ V via HMMA ---------------------------
__global__ void __launch_bounds__(256) k5_kv(const float* __restrict__ V) {
    int nh = blockIdx.x, tile = blockIdx.y;    // 32 tiles x 128 rows
    int t = threadIdx.x;
    const int base = head_base(nh);
    const size_t sbase = (size_t)nh * L_ * D_;
    int s0g = tile * 128;

    __shared__ unsigned a_pk[64*72];   // (w*sk) packed pairs along s: [sp][d]
    __shared__ unsigned b_pk[64*72];   // V packed pairs along s:      [sp][e]
    __shared__ __half2 wh_sh[64];

    if (t < 64) {
        float w0 = g_cr[nh*L_ + s0g + 2*t];
        float w1 = g_cr[nh*L_ + s0g + 2*t + 1];
        wh_sh[t] = __floats2half2_rn(w0, w1);
    }
    __syncthreads();

    // build a_pk from g_sk (transpose-pack along s, fold weights)
    {
        const unsigned* pk32 = (const unsigned*)(g_sk + sbase);
        #pragma unroll
        for (int p = 0; p < 16; p++) {
            int i = t + p*256;
            int d = i & 63, sp = i >> 6;
            int s = s0g + 2*sp;
            unsigned u0 = pk32[(size_t)s * 32 + (d >> 1)];
            unsigned u1 = pk32[(size_t)(s+1) * 32 + (d >> 1)];
            unsigned pr = (d & 1) ? __byte_perm(u0, u1, 0x7632)
                                  : __byte_perm(u0, u1, 0x5410);
            __half2 h = __hmul2(*reinterpret_cast<__half2*>(&pr), wh_sh[sp]);
            a_pk[sp*72 + d] = *reinterpret_cast<unsigned*>(&h);
        }
    }
    // build b_pk from V (fp32 -> fp16 pairs along s)
    {
        #pragma unroll
        for (int p = 0; p < 16; p++) {
            int i = t + p*256;
            int e = i & 63, sp = i >> 6;
            int s = s0g + 2*sp;
            float f0 = V[base + s*RS + e];
            float f1 = V[base + (s+1)*RS + e];
            __half2 h = __floats2half2_rn(f0, f1);
            b_pk[sp*72 + e] = *reinterpret_cast<unsigned*>(&h);
        }
    }
    __syncthreads();

    int w = t >> 5, l = t & 31;
    int mt = w & 3, nhf = w >> 2;
    int grow = l >> 2, kc = l & 3;
    float c[4][4] = {};

    #pragma unroll
    for (int kt = 0; kt < 8; kt++) {
        int spA = (kt*8 + kc) * 72;
        int spB = (kt*8 + kc + 4) * 72;
        unsigned a0 = a_pk[spA + mt*16 + grow];
        unsigned a1 = a_pk[spA + mt*16 + grow + 8];
        unsigned a2 = a_pk[spB + mt*16 + grow];
        unsigned a3 = a_pk[spB + mt*16 + grow + 8];
        #pragma unroll
        for (int nt = 0; nt < 4; nt++) {
            unsigned b0 = b_pk[spA + nhf*32 + nt*8 + grow];
            unsigned b1 = b_pk[spB + nhf*32 + nt*8 + grow];
            mma16816(c[nt][0], c[nt][1], c[nt][2], c[nt][3],
                     a0, a1, a2, a3, b0, b1);
        }
    }
    int drow = mt*16 + grow;
    #pragma unroll
    for (int nt = 0; nt < 4; nt++) {
        int e = nhf*32 + nt*8 + kc*2;
        float* dst = &g_kv[nh*4096 + drow*64 + e];
        atomicAdd(dst,     c[nt][0]);
        atomicAdd(dst + 1, c[nt][1]);
        atomicAdd(dst + 512,     c[nt][2]);   // (drow+8)*64
        atomicAdd(dst + 512 + 1, c[nt][3]);
    }
}

// ---------------- K6: out = (sq @ kv) * rowfac via HMMA ---------------------
__global__ void __launch_bounds__(256) k6_out(float* __restrict__ O) {
    int nh = blockIdx.x, tile = blockIdx.y;    // 32 tiles x 128 rows
    int t = threadIdx.x;
    const int base = head_base(nh);
    const size_t sbase = (size_t)nh * L_ * D_;
    int r0g = tile * 128;

    __shared__ unsigned sq_sh[128*36];   // fp16 pairs along d: [r][d/2], pitch 36
    __shared__ unsigned kv_pk[32*72];    // kv packed pairs along d: [dp][e]
    __shared__ float rf[128];

    if (t < 128) rf[t] = g_rowfac[nh*L_ + r0g + t];
    // copy sq tile (128 rows x 32 b32)
    {
        const uint4* p = (const uint4*)(g_sq + sbase + (size_t)r0g * D_);
        #pragma unroll
        for (int pass = 0; pass < 4; pass++) {
            int i = t + pass*256;
            uint4 u = p[i];
            int row = i >> 3, j = i & 7;
            *(uint4*)&sq_sh[row*36 + j*4] = u;
        }
    }
    // build kv_pk (fp32 kv -> fp16 pairs along d)
    {
        #pragma unroll
        for (int p = 0; p < 8; p++) {
            int i = t + p*256;
            int e = i & 63, dp = i >> 6;
            float f0 = g_kv[nh*4096 + (2*dp)*64 + e];
            float f1 = g_kv[nh*4096 + (2*dp+1)*64 + e];
            __half2 h = __floats2half2_rn(f0, f1);
            kv_pk[dp*72 + e] = *reinterpret_cast<unsigned*>(&h);
        }
    }
    __syncthreads();

    int w = t >> 5, l = t & 31;
    int rb = w * 16;
    int grow = l >> 2, kc = l & 3;
    float c[8][4] = {};

    #pragma unroll
    for (int kt = 0; kt < 4; kt++) {
        unsigned a0 = sq_sh[(rb + grow)*36     + kt*8 + kc];
        unsigned a1 = sq_sh[(rb + grow + 8)*36 + kt*8 + kc];
        unsigned a2 = sq_sh[(rb + grow)*36     + kt*8 + kc + 4];
        unsigned a3 = sq_sh[(rb + grow + 8)*36 + kt*8 + kc + 4];
        int dpA = (kt*8 + kc) * 72;
        int dpB = (kt*8 + kc + 4) * 72;
        #pragma unroll
        for (int nt = 0; nt < 8; nt++) {
            unsigned b0 = kv_pk[dpA + nt*8 + grow];
            unsigned b1 = kv_pk[dpB + nt*8 + grow];
            mma16816(c[nt][0], c[nt][1], c[nt][2], c[nt][3],
                     a0, a1, a2, a3, b0, b1);
        }
    }
    int rA = r0g + rb + grow;
    float f0 = rf[rb + grow], f1 = rf[rb + grow + 8];
    #pragma unroll
    for (int nt = 0; nt < 8; nt++) {
        int e = nt*8 + kc*2;
        float2 o0; o0.x = c[nt][0] * f0; o0.y = c[nt][1] * f0;
        float2 o1; o1.x = c[nt][2] * f1; o1.y = c[nt][3] * f1;
        *(float2*)(O + base + rA*RS + e)       = o0;
        *(float2*)(O + base + (rA+8)*RS + e)   = o1;
    }
}

// ---------------- launch ----------------------------------------------------
extern "C" void kernel_launch(void* const* d_in, const int* in_sizes, int n_in,
                              void* d_out, int out_size) {
    const float* Q = (const float*)d_in[0];
    const float* K = (const float*)d_in[1];
    const float* V = (const float*)d_in[2];
    float* O = (float*)d_out;

    k1_sums   <<<dim3(NH, 16), 256>>>(Q, K);
    k2_norm   <<<dim3(NH, 16), 256>>>();
    k3_refine <<<dim3(NH, 16), 256>>>();
    k4_weights<<<dim3(NH),     256>>>();
    k5_kv     <<<dim3(NH, 32), 256>>>(V);
    k6_out    <<<dim3(NH, 32), 256>>>(O);
}